// round 8
// baseline (speedup 1.0000x reference)
#include <cuda_runtime.h>
#include <cuda_fp16.h>
#include <math.h>
#include <stdint.h>

// Problem constants
#define B_  2
#define L_  1024
#define DM  1024
#define DI  2048
#define DS  16
#define DTR 64
#define KC  4
#define BL  (B_*L_)   // 2048

// ---------------- scratch (device globals) -----------------------------------
__device__ float g_xc [BL*DI];
__device__ float g_z  [BL*DI];
__device__ float g_xca[BL*DI];
__device__ float g_dBC[BL*96];
__device__ float g_del[BL*DI];
__device__ float g_u  [BL*DI];

// fp16 operands for tensor-core GEMMs (A split hi/lo, B rounded once)
__device__ __half g_xh [BL*DM];
__device__ __half g_xl [BL*DM];
__device__ __half g_wih[2*DI*DM];
__device__ __half g_uh [BL*DI];
__device__ __half g_ul [BL*DI];
__device__ __half g_woh[DM*DI];

// ======================= PTX helpers (sm_80 baseline) =========================
__device__ __forceinline__ uint32_t smem_u32(const void* p){
    uint32_t a;
    asm("{ .reg .u64 t; cvta.to.shared.u64 t, %1; cvt.u32.u64 %0, t; }" : "=r"(a) : "l"(p));
    return a;
}
__device__ __forceinline__ void cp16(uint32_t dst, const void* src){
    asm volatile("cp.async.cg.shared.global [%0], [%1], 16;" :: "r"(dst), "l"(src));
}
__device__ __forceinline__ void cp_commit(){ asm volatile("cp.async.commit_group;" ::: "memory"); }
template<int N> __device__ __forceinline__ void cp_wait(){
    asm volatile("cp.async.wait_group %0;" :: "n"(N) : "memory");
}
__device__ __forceinline__ void ldsm_x4(uint32_t* r, uint32_t addr){
    asm volatile("ldmatrix.sync.aligned.m8n8.x4.shared.b16 {%0,%1,%2,%3}, [%4];"
        : "=r"(r[0]), "=r"(r[1]), "=r"(r[2]), "=r"(r[3]) : "r"(addr));
}
__device__ __forceinline__ void mma16816(float* c, const uint32_t* a, const uint32_t* b){
    asm volatile(
        "mma.sync.aligned.m16n8k16.row.col.f32.f16.f16.f32 "
        "{%0,%1,%2,%3}, {%4,%5,%6,%7}, {%8,%9}, {%0,%1,%2,%3};"
        : "+f"(c[0]), "+f"(c[1]), "+f"(c[2]), "+f"(c[3])
        : "r"(a[0]), "r"(a[1]), "r"(a[2]), "r"(a[3]), "r"(b[0]), "r"(b[1]));
}

// ========= hybrid GEMM: C[M,N] = A[M,K]*B[N,K]^T =============================
// blockIdx.x <  nsplit : HMMA fp16x2 path (128x128 CTA, 8 warps, warp 64x32)
// blockIdx.x >= nsplit : FFMA fp32 path  (exact; reads original fp32 operands)
// MODE 0: plain store. MODE 1: split g_xc/g_z at DI boundary.
#define RSB   80
#define ARR   (128*RSB)
#define STG   (3*ARR)
#define MMA_SMEM (2*STG)     // 61440 (covers FFMA's 8KB need too)

template<int MODE>
__global__ __launch_bounds__(256)
void hybrid_gemm(const __half* __restrict__ Ah, const __half* __restrict__ Al,
                 const __half* __restrict__ Bh,
                 const float* __restrict__ Af, const float* __restrict__ Wf,
                 int Kdim, float* __restrict__ C, int ldc, int nsplit)
{
    extern __shared__ char sraw[];
    const int tid = threadIdx.x;
    const int bm  = blockIdx.y * 128, bn = blockIdx.x * 128;

    if ((int)blockIdx.x < nsplit) {
        // ===================== HMMA path (R6 verbatim) =======================
        const uint32_t base = smem_u32(sraw);
        const int wid  = tid >> 5, lane = tid & 31;
        const int wm   = wid & 1;
        const int wn   = wid >> 1;

        float acc[4][4][4];
#pragma unroll
        for (int i = 0; i < 4; i++)
#pragma unroll
            for (int j = 0; j < 4; j++)
#pragma unroll
                for (int q = 0; q < 4; q++) acc[i][j][q] = 0.f;

        const int  row = tid >> 1;
        const int  hs  = tid & 1;
        const char* sAh = (const char*)(Ah + (size_t)(bm + row) * Kdim) + hs*32;
        const char* sAl = (const char*)(Al + (size_t)(bm + row) * Kdim) + hs*32;
        const char* sBh = (const char*)(Bh + (size_t)(bn + row) * Kdim) + hs*32;
        const uint32_t dst0 = base + row*RSB + hs*32;

        #define LOAD_STAGE(c, st) do {                                          \
            uint32_t d = dst0 + (st)*STG;                                        \
            size_t   g = (size_t)(c)*64;                                         \
            cp16(d,          sAh+g); cp16(d+16,          sAh+g+16);              \
            cp16(d+ARR,      sAl+g); cp16(d+ARR+16,      sAl+g+16);              \
            cp16(d+2*ARR,    sBh+g); cp16(d+2*ARR+16,    sBh+g+16);              \
        } while(0)

        LOAD_STAGE(0, 0);
        cp_commit();

        const uint32_t aoff = base + (uint32_t)((wm*64 + (lane & 15))*RSB + (lane >> 4)*16);
        const uint32_t boff = base + 2*ARR + (uint32_t)((wn*32 + (lane & 15))*RSB + (lane >> 4)*16);

        const int NCH = Kdim >> 5;
        for (int c = 0; c < NCH; c++){
            const int st = c & 1;
            if (c + 1 < NCH) LOAD_STAGE(c + 1, st ^ 1);
            cp_commit();
            cp_wait<1>();
            __syncthreads();

            const uint32_t so = (uint32_t)st * STG;
#pragma unroll
            for (int ks = 0; ks < 2; ks++){
                uint32_t ah[4][4], al[4][4];
#pragma unroll
                for (int i = 0; i < 4; i++){
                    ldsm_x4(ah[i], aoff + so +       (uint32_t)(i*16*RSB + ks*32));
                    ldsm_x4(al[i], aoff + so + ARR + (uint32_t)(i*16*RSB + ks*32));
                }
                uint32_t bh[2][4];
#pragma unroll
                for (int jp = 0; jp < 2; jp++)
                    ldsm_x4(bh[jp], boff + so + (uint32_t)(jp*16*RSB + ks*32));
#pragma unroll
                for (int i = 0; i < 4; i++){
#pragma unroll
                    for (int j = 0; j < 4; j++){
                        uint32_t bfh[2] = { bh[j>>1][j&1], bh[j>>1][2+(j&1)] };
                        mma16816(acc[i][j], ah[i], bfh);
                        mma16816(acc[i][j], al[i], bfh);
                    }
                }
            }
            __syncthreads();
        }
        #undef LOAD_STAGE

        float* Cb; int n0; int ld;
        if (MODE == 1){
            if (bn < DI){ Cb = g_xc; n0 = bn; } else { Cb = g_z; n0 = bn - DI; }
            ld = DI;
        } else { Cb = C; n0 = bn; ld = ldc; }

        const int g = lane >> 2, t = lane & 3;
#pragma unroll
        for (int i = 0; i < 4; i++){
            const int r0 = bm + wm*64 + i*16 + g;
#pragma unroll
            for (int j = 0; j < 4; j++){
                const int col = n0 + wn*32 + j*8 + t*2;
                float2 v0 = make_float2(acc[i][j][0], acc[i][j][1]);
                float2 v1 = make_float2(acc[i][j][2], acc[i][j][3]);
                *(float2*)(Cb + (size_t)r0       * ld + col) = v0;
                *(float2*)(Cb + (size_t)(r0 + 8) * ld + col) = v1;
            }
        }
    } else {
        // ===================== FFMA path (R1 gemm_big, exact fp32) ===========
        float* As = (float*)sraw;        // [8][128]
        float* Bs = As + 8*128;          // [8][128]

        float acc[8][8];
#pragma unroll
        for (int i = 0; i < 8; i++)
#pragma unroll
            for (int j = 0; j < 8; j++) acc[i][j] = 0.f;

        const int arow = tid >> 1;
        const int acol = (tid & 1) * 4;
        const int trow = (tid >> 4) * 8;
        const int tcol = (tid & 15) * 8;

        const float* Aptr = Af + (size_t)(bm + arow) * Kdim + acol;
        const float* Wptr = Wf + (size_t)(bn + arow) * Kdim + acol;

        for (int kt = 0; kt < Kdim; kt += 8) {
            float4 av = *(const float4*)(Aptr + kt);
            float4 wv = *(const float4*)(Wptr + kt);
            As[(acol+0)*128 + arow] = av.x; As[(acol+1)*128 + arow] = av.y;
            As[(acol+2)*128 + arow] = av.z; As[(acol+3)*128 + arow] = av.w;
            Bs[(acol+0)*128 + arow] = wv.x; Bs[(acol+1)*128 + arow] = wv.y;
            Bs[(acol+2)*128 + arow] = wv.z; Bs[(acol+3)*128 + arow] = wv.w;
            __syncthreads();

#pragma unroll
            for (int kk = 0; kk < 8; kk++) {
                float4 a0 = *(const float4*)&As[kk*128 + trow];
                float4 a1 = *(const float4*)&As[kk*128 + trow+4];
                float4 b0 = *(const float4*)&Bs[kk*128 + tcol];
                float4 b1 = *(const float4*)&Bs[kk*128 + tcol+4];
                float ar[8] = {a0.x,a0.y,a0.z,a0.w,a1.x,a1.y,a1.z,a1.w};
                float br[8] = {b0.x,b0.y,b0.z,b0.w,b1.x,b1.y,b1.z,b1.w};
#pragma unroll
                for (int i = 0; i < 8; i++)
#pragma unroll
                    for (int j = 0; j < 8; j++)
                        acc[i][j] = fmaf(ar[i], br[j], acc[i][j]);
            }
            __syncthreads();
        }

        float* Cb; int n0; int ld;
        if (MODE == 1){
            if (bn < DI){ Cb = g_xc; n0 = bn; } else { Cb = g_z; n0 = bn - DI; }
            ld = DI;
        } else { Cb = C; n0 = bn; ld = ldc; }

#pragma unroll
        for (int i = 0; i < 8; i++) {
            const int m = bm + trow + i;
#pragma unroll
            for (int j = 0; j < 8; j++) {
                Cb[(size_t)m * ld + (n0 + tcol + j)] = acc[i][j];
            }
        }
    }
}

// ---------------- fp32 -> (hi,lo) fp16 split ----------------------------------
__global__ __launch_bounds__(256)
void split_fp16(const float* __restrict__ in, __half* __restrict__ hi,
                __half* __restrict__ lo, int n4)
{
    int i = blockIdx.x * blockDim.x + threadIdx.x;
    if (i >= n4) return;
    float4 v = ((const float4*)in)[i];
    float a[4] = {v.x, v.y, v.z, v.w};
    __half h[4], l[4];
    #pragma unroll
    for (int k = 0; k < 4; k++){
        h[k] = __float2half_rn(a[k]);
        l[k] = __float2half_rn(a[k] - __half2float(h[k]));
    }
    ((__half2*)hi)[2*i]   = __halves2half2(h[0], h[1]);
    ((__half2*)hi)[2*i+1] = __halves2half2(h[2], h[3]);
    ((__half2*)lo)[2*i]   = __halves2half2(l[0], l[1]);
    ((__half2*)lo)[2*i+1] = __halves2half2(l[2], l[3]);
}

// ---------------- fp32 -> fp16 round (weights) --------------------------------
__global__ __launch_bounds__(256)
void cvt_fp16(const float* __restrict__ in, __half* __restrict__ out, int n4)
{
    int i = blockIdx.x * blockDim.x + threadIdx.x;
    if (i >= n4) return;
    float4 v = ((const float4*)in)[i];
    ((__half2*)out)[2*i]   = __halves2half2(__float2half_rn(v.x), __float2half_rn(v.y));
    ((__half2*)out)[2*i+1] = __halves2half2(__float2half_rn(v.z), __float2half_rn(v.w));
}

// ---------------- fp32 SIMT GEMM (delta GEMM, K=64) ---------------------------
__global__ __launch_bounds__(256)
void gemm_delta(const float* __restrict__ A, int lda,
                const float* __restrict__ W, int Kdim,
                float* __restrict__ C, int ldc,
                const float* __restrict__ bias)
{
    const int bm = blockIdx.y * 128;
    const int bn = blockIdx.x * 128;

    __shared__ float As[8][128];
    __shared__ float Bs[8][128];

    float acc[8][8];
#pragma unroll
    for (int i = 0; i < 8; i++)
#pragma unroll
        for (int j = 0; j < 8; j++) acc[i][j] = 0.f;

    const int tid  = threadIdx.x;
    const int arow = tid >> 1;
    const int acol = (tid & 1) * 4;
    const int trow = (tid >> 4) * 8;
    const int tcol = (tid & 15) * 8;

    const float* Aptr = A + (size_t)(bm + arow) * lda + acol;
    const float* Wptr = W + (size_t)(bn + arow) * Kdim + acol;

    for (int kt = 0; kt < Kdim; kt += 8) {
        float4 av = *(const float4*)(Aptr + kt);
        float4 wv = *(const float4*)(Wptr + kt);
        As[acol+0][arow] = av.x; As[acol+1][arow] = av.y;
        As[acol+2][arow] = av.z; As[acol+3][arow] = av.w;
        Bs[acol+0][arow] = wv.x; Bs[acol+1][arow] = wv.y;
        Bs[acol+2][arow] = wv.z; Bs[acol+3][arow] = wv.w;
        __syncthreads();

#pragma unroll
        for (int kk = 0; kk < 8; kk++) {
            float4 a0 = *(const float4*)&As[kk][trow];
            float4 a1 = *(const float4*)&As[kk][trow+4];
            float4 b0 = *(const float4*)&Bs[kk][tcol];
            float4 b1 = *(const float4*)&Bs[kk][tcol+4];
            float ar[8] = {a0.x,a0.y,a0.z,a0.w,a1.x,a1.y,a1.z,a1.w};
            float br[8] = {b0.x,b0.y,b0.z,b0.w,b1.x,b1.y,b1.z,b1.w};
#pragma unroll
            for (int i = 0; i < 8; i++)
#pragma unroll
                for (int j = 0; j < 8; j++)
                    acc[i][j] = fmaf(ar[i], br[j], acc[i][j]);
        }
        __syncthreads();
    }

#pragma unroll
    for (int i = 0; i < 8; i++) {
        const int m = bm + trow + i;
#pragma unroll
        for (int j = 0; j < 8; j++) {
            const int n = bn + tcol + j;
            float v = acc[i][j] + bias[n];
            float sp = (v > 20.f) ? v : log1pf(__expf(v));
            C[(size_t)m * ldc + n] = sp;
        }
    }
}

// ---------------- small tiled GEMM for dBC (N=96) ----------------------------
__global__ __launch_bounds__(256)
void gemm_small(const float* __restrict__ A, int lda,
                const float* __restrict__ W, int Kdim,
                float* __restrict__ C, int ldc)
{
    const int bm = blockIdx.y * 32;
    const int bn = blockIdx.x * 32;

    __shared__ float As[32][33];
    __shared__ float Ws[32][33];

    float acc[2][2] = {{0.f,0.f},{0.f,0.f}};

    const int tid  = threadIdx.x;
    const int lrow = tid >> 3;
    const int lcol = (tid & 7) * 4;
    const int tm   = (tid >> 4) * 2;
    const int tn   = (tid & 15) * 2;

    for (int kt = 0; kt < Kdim; kt += 32) {
        float4 av = *(const float4*)(A + (size_t)(bm + lrow) * lda + kt + lcol);
        float4 wv = *(const float4*)(W + (size_t)(bn + lrow) * Kdim + kt + lcol);
        As[lcol+0][lrow] = av.x; As[lcol+1][lrow] = av.y;
        As[lcol+2][lrow] = av.z; As[lcol+3][lrow] = av.w;
        Ws[lcol+0][lrow] = wv.x; Ws[lcol+1][lrow] = wv.y;
        Ws[lcol+2][lrow] = wv.z; Ws[lcol+3][lrow] = wv.w;
        __syncthreads();

#pragma unroll
        for (int kk = 0; kk < 32; kk++) {
            float a0 = As[kk][tm], a1 = As[kk][tm+1];
            float b0 = Ws[kk][tn], b1 = Ws[kk][tn+1];
            acc[0][0] = fmaf(a0, b0, acc[0][0]);
            acc[0][1] = fmaf(a0, b1, acc[0][1]);
            acc[1][0] = fmaf(a1, b0, acc[1][0]);
            acc[1][1] = fmaf(a1, b1, acc[1][1]);
        }
        __syncthreads();
    }

#pragma unroll
    for (int i = 0; i < 2; i++)
#pragma unroll
        for (int j = 0; j < 2; j++)
            C[(size_t)(bm + tm + i) * ldc + (bn + tn + j)] = acc[i][j];
}

// ---------------- depthwise causal conv (K=4) + bias + SiLU ------------------
__global__ __launch_bounds__(256)
void conv_silu_kernel(const float* __restrict__ cw, const float* __restrict__ cb)
{
    int idx = blockIdx.x * blockDim.x + threadIdx.x;
    if (idx >= BL * DI) return;
    int d  = idx % DI;
    int bl = idx / DI;
    int l  = bl % L_;
    int b  = bl / L_;

    float s = cb[d];
    const float* base = g_xc + (size_t)b * L_ * DI + d;
#pragma unroll
    for (int j = 0; j < KC; j++) {
        int ll = l + j - (KC - 1);
        if (ll >= 0) s = fmaf(base[(size_t)ll * DI], cw[d * KC + j], s);
    }
    g_xca[idx] = s / (1.f + __expf(-s));
}

// ---------------- selective scan + gate (R6 version; +fp32 u store) -----------
__global__ __launch_bounds__(256)
void scan_kernel(const float* __restrict__ A_log, const float* __restrict__ Dp)
{
    const int gtid = blockIdx.x * blockDim.x + threadIdx.x;
    const int warp = gtid >> 5;
    const int lane = threadIdx.x & 31;
    const int half = lane >> 4;
    const int n    = lane & 15;
    const int c    = warp * 2 + half;
    const int b    = c / DI;
    const int d    = c % DI;

    const float Aval = -__expf(A_log[d * DS + n]);
    const float dp   = Dp[d];

    const size_t rbase = (size_t)b * L_ * DI + d;
    const float* pD = g_del + rbase;
    const float* pX = g_xca + rbase;
    const float* pZ = g_z   + rbase;
    const float* pB = g_dBC + (size_t)b * L_ * 96 + DTR + n;
    const float* pC = g_dBC + (size_t)b * L_ * 96 + DTR + DS + n;
    __half* pUh = g_uh + rbase;
    __half* pUl = g_ul + rbase;
    float*  pU  = g_u  + rbase;

    float h = 0.f;
    float dlt = pD[0], xv = pX[0], zv = pZ[0], Bn = pB[0], Cn = pC[0];

    for (int l = 0; l < L_; l++) {
        const int ln = (l + 1 < L_) ? (l + 1) : l;
        float dlt_n = pD[(size_t)ln * DI];
        float xv_n  = pX[(size_t)ln * DI];
        float zv_n  = pZ[(size_t)ln * DI];
        float Bn_n  = pB[(size_t)ln * 96];
        float Cn_n  = pC[(size_t)ln * 96];

        float a = __expf(dlt * Aval);
        h = fmaf(a, h, dlt * Bn * xv);
        float p = h * Cn;
        p += __shfl_xor_sync(0xffffffffu, p, 8);
        p += __shfl_xor_sync(0xffffffffu, p, 4);
        p += __shfl_xor_sync(0xffffffffu, p, 2);
        p += __shfl_xor_sync(0xffffffffu, p, 1);
        if (n == 0) {
            float y  = fmaf(dp, xv, p);
            float sz = zv / (1.f + __expf(-zv));
            float u  = y * sz;
            __half uh = __float2half_rn(u);
            __half ul = __float2half_rn(u - __half2float(uh));
            pUh[(size_t)l * DI] = uh;
            pUl[(size_t)l * DI] = ul;
            pU [(size_t)l * DI] = u;
        }
        dlt = dlt_n; xv = xv_n; zv = zv_n; Bn = Bn_n; Cn = Cn_n;
    }
}

// ---------------- launch ------------------------------------------------------
extern "C" void kernel_launch(void* const* d_in, const int* in_sizes, int n_in,
                              void* d_out, int out_size)
{
    const float* x      = (const float*)d_in[0];
    const float* W_in   = (const float*)d_in[1];
    const float* conv_w = (const float*)d_in[2];
    const float* conv_b = (const float*)d_in[3];
    const float* W_x    = (const float*)d_in[4];
    const float* W_dt   = (const float*)d_in[5];
    const float* b_dt   = (const float*)d_in[6];
    const float* A_log  = (const float*)d_in[7];
    const float* Dp     = (const float*)d_in[8];
    const float* W_out  = (const float*)d_in[9];
    float* out = (float*)d_out;

    float* p_xca; cudaGetSymbolAddress((void**)&p_xca, g_xca);
    float* p_dBC; cudaGetSymbolAddress((void**)&p_dBC, g_dBC);
    float* p_del; cudaGetSymbolAddress((void**)&p_del, g_del);
    float* p_u;   cudaGetSymbolAddress((void**)&p_u,   g_u);

    __half *p_xh, *p_xl, *p_wih, *p_uh, *p_ul, *p_woh;
    cudaGetSymbolAddress((void**)&p_xh,  g_xh);
    cudaGetSymbolAddress((void**)&p_xl,  g_xl);
    cudaGetSymbolAddress((void**)&p_wih, g_wih);
    cudaGetSymbolAddress((void**)&p_uh,  g_uh);
    cudaGetSymbolAddress((void**)&p_ul,  g_ul);
    cudaGetSymbolAddress((void**)&p_woh, g_woh);

    cudaFuncSetAttribute(hybrid_gemm<0>, cudaFuncAttributeMaxDynamicSharedMemorySize, MMA_SMEM);
    cudaFuncSetAttribute(hybrid_gemm<1>, cudaFuncAttributeMaxDynamicSharedMemorySize, MMA_SMEM);

    // 0) split x (hi/lo) and round W_in to fp16
    {
        int n4 = (BL * DM) / 4;
        split_fp16<<<(n4 + 255) / 256, 256>>>(x, p_xh, p_xl, n4);
        n4 = (2 * DI * DM) / 4;
        cvt_fp16<<<(n4 + 255) / 256, 256>>>(W_in, p_wih, n4);
    }
    // 1) xz = x @ W_in^T  (hybrid: 24 HMMA + 8 FFMA N-tiles) -> g_xc / g_z
    {
        dim3 grid(2 * DI / 128, BL / 128);   // (32, 16)
        hybrid_gemm<1><<<grid, 256, MMA_SMEM>>>(p_xh, p_xl, p_wih,
                                                x, W_in, DM, nullptr, 0, 24);
    }
    // 2) depthwise causal conv + bias + silu -> g_xca
    {
        int total = BL * DI;
        conv_silu_kernel<<<(total + 255) / 256, 256>>>(conv_w, conv_b);
    }
    // 3) dBC = xca @ W_x^T   [BL,96]
    {
        dim3 grid(96 / 32, BL / 32);
        gemm_small<<<grid, 256>>>(p_xca, DI, W_x, DI, p_dBC, 96);
    }
    // 4) delta = softplus(dBC[:, :64] @ W_dt^T + b_dt)  [BL, DI]
    {
        dim3 grid(DI / 128, BL / 128);
        gemm_delta<<<grid, 256>>>(p_dBC, 96, W_dt, DTR, p_del, DI, b_dt);
    }
    // 5) selective scan + D skip + gate -> g_uh/g_ul (+ fp32 g_u)
    {
        scan_kernel<<<(B_ * DI / 2) * 32 / 256, 256>>>(A_log, Dp);
    }
    // 5b) round W_out to fp16
    {
        int n4 = (DM * DI) / 4;
        cvt_fp16<<<(n4 + 255) / 256, 256>>>(W_out, p_woh, n4);
    }
    // 6) out = u @ W_out^T  (hybrid: 6 HMMA + 2 FFMA N-tiles)
    {
        dim3 grid(DM / 128, BL / 128);       // (8, 16)
        hybrid_gemm<0><<<grid, 256, MMA_SMEM>>>(p_uh, p_ul, p_woh,
                                                p_u, W_out, DI, out, DM, 6);
    }
}

// round 9
// speedup vs baseline: 1.3568x; 1.3568x over previous
#include <cuda_runtime.h>
#include <cuda_fp16.h>
#include <math.h>
#include <stdint.h>

// Problem constants
#define B_  2
#define L_  1024
#define DM  1024
#define DI  2048
#define DS  16
#define DTR 64
#define KC  4
#define BL  (B_*L_)   // 2048

// ---------------- scratch (device globals) -----------------------------------
__device__ float g_xc [BL*DI];
__device__ float g_z  [BL*DI];
__device__ float g_xca[BL*DI];
__device__ float g_dBC[BL*96];
__device__ float g_del[BL*DI];

// fp16 operands for tensor-core GEMMs (A split hi/lo, B rounded once)
__device__ __half g_xh [BL*DM];
__device__ __half g_xl [BL*DM];
__device__ __half g_wih[2*DI*DM];
__device__ __half g_uh [BL*DI];
__device__ __half g_ul [BL*DI];
__device__ __half g_woh[DM*DI];

// ======================= PTX helpers (sm_80 baseline) =========================
__device__ __forceinline__ uint32_t smem_u32(const void* p){
    uint32_t a;
    asm("{ .reg .u64 t; cvta.to.shared.u64 t, %1; cvt.u32.u64 %0, t; }" : "=r"(a) : "l"(p));
    return a;
}
__device__ __forceinline__ void cp16(uint32_t dst, const void* src){
    asm volatile("cp.async.cg.shared.global [%0], [%1], 16;" :: "r"(dst), "l"(src));
}
__device__ __forceinline__ void cp_commit(){ asm volatile("cp.async.commit_group;" ::: "memory"); }
template<int N> __device__ __forceinline__ void cp_wait(){
    asm volatile("cp.async.wait_group %0;" :: "n"(N) : "memory");
}
__device__ __forceinline__ void ldsm_x4(uint32_t* r, uint32_t addr){
    asm volatile("ldmatrix.sync.aligned.m8n8.x4.shared.b16 {%0,%1,%2,%3}, [%4];"
        : "=r"(r[0]), "=r"(r[1]), "=r"(r[2]), "=r"(r[3]) : "r"(addr));
}
__device__ __forceinline__ void mma16816(float* c, const uint32_t* a, const uint32_t* b){
    asm volatile(
        "mma.sync.aligned.m16n8k16.row.col.f32.f16.f16.f32 "
        "{%0,%1,%2,%3}, {%4,%5,%6,%7}, {%8,%9}, {%0,%1,%2,%3};"
        : "+f"(c[0]), "+f"(c[1]), "+f"(c[2]), "+f"(c[3])
        : "r"(a[0]), "r"(a[1]), "r"(a[2]), "r"(a[3]), "r"(b[0]), "r"(b[1]));
}

// ============ HMMA GEMM v3: CTA tile 128x64, 4 warps (128 thr), warp 64x32 ====
// fp16x2: C = (Ah+Al)*Bh.  K-chunk 32, double buffered cp.async.
// MODE 0: plain store. MODE 1: split g_xc/g_z at DI boundary.
#define RSB   80
#define ARR   (128*RSB)              // 10240 bytes (A arrays: 128 rows)
#define BARR  (64*RSB)               // 5120 bytes  (B array: 64 rows)
#define STG   (2*ARR + BARR)         // 25600 bytes per stage
#define MMA_SMEM (2*STG)             // 51200

template<int MODE>
__global__ __launch_bounds__(128)
void mma_gemm(const __half* __restrict__ Ah, const __half* __restrict__ Al,
              const __half* __restrict__ Bh,
              int Kdim, float* __restrict__ C, int ldc)
{
    extern __shared__ char sraw[];
    const uint32_t base = smem_u32(sraw);

    const int tid  = threadIdx.x;
    const int wid  = tid >> 5, lane = tid & 31;
    const int wm   = wid & 1;          // 2 warp-rows of 64
    const int wn   = wid >> 1;         // 2 warp-cols of 32
    const int bm   = blockIdx.y * 128, bn = blockIdx.x * 64;

    float acc[4][4][4];
#pragma unroll
    for (int i = 0; i < 4; i++)
#pragma unroll
        for (int j = 0; j < 4; j++)
#pragma unroll
            for (int q = 0; q < 4; q++) acc[i][j][q] = 0.f;

    // stage loaders: thread t owns A row t (64B); threads 0-63 also own B row t
    const char* sAh = (const char*)(Ah + (size_t)(bm + tid) * Kdim);
    const char* sAl = (const char*)(Al + (size_t)(bm + tid) * Kdim);
    const char* sBh = (const char*)(Bh + (size_t)(bn + (tid & 63)) * Kdim);
    const uint32_t dstA = base + tid*RSB;
    const uint32_t dstB = base + 2*ARR + (tid & 63)*RSB;
    const bool doB = tid < 64;

    #define LOAD_STAGE(c, st) do {                                          \
        uint32_t so_ = (st)*STG;                                             \
        size_t   g  = (size_t)(c)*64;                                        \
        _Pragma("unroll")                                                    \
        for (int j = 0; j < 4; j++){                                         \
            cp16(dstA + so_ +       j*16, sAh + g + j*16);                   \
            cp16(dstA + so_ + ARR + j*16, sAl + g + j*16);                   \
        }                                                                    \
        if (doB){                                                            \
            _Pragma("unroll")                                                \
            for (int j = 0; j < 4; j++)                                      \
                cp16(dstB + so_ + j*16, sBh + g + j*16);                     \
        }                                                                    \
    } while(0)

    LOAD_STAGE(0, 0);
    cp_commit();

    const uint32_t aoff = base + (uint32_t)((wm*64 + (lane & 15))*RSB + (lane >> 4)*16);
    const uint32_t boff = base + 2*ARR + (uint32_t)((wn*32 + (lane & 15))*RSB + (lane >> 4)*16);

    const int NCH = Kdim >> 5;
    for (int c = 0; c < NCH; c++){
        const int st = c & 1;
        if (c + 1 < NCH) LOAD_STAGE(c + 1, st ^ 1);
        cp_commit();
        cp_wait<1>();
        __syncthreads();

        const uint32_t so = (uint32_t)st * STG;
#pragma unroll
        for (int ks = 0; ks < 2; ks++){
            uint32_t ah[4][4], al[4][4];
#pragma unroll
            for (int i = 0; i < 4; i++){
                ldsm_x4(ah[i], aoff + so +       (uint32_t)(i*16*RSB + ks*32));
                ldsm_x4(al[i], aoff + so + ARR + (uint32_t)(i*16*RSB + ks*32));
            }
            uint32_t bh[2][4];
#pragma unroll
            for (int jp = 0; jp < 2; jp++)
                ldsm_x4(bh[jp], boff + so + (uint32_t)(jp*16*RSB + ks*32));
#pragma unroll
            for (int i = 0; i < 4; i++){
#pragma unroll
                for (int j = 0; j < 4; j++){
                    uint32_t bfh[2] = { bh[j>>1][j&1], bh[j>>1][2+(j&1)] };
                    mma16816(acc[i][j], ah[i], bfh);
                    mma16816(acc[i][j], al[i], bfh);
                }
            }
        }
        __syncthreads();
    }
    #undef LOAD_STAGE

    // ---- epilogue ----
    float* Cb; int n0; int ld;
    if (MODE == 1){
        if (bn < DI){ Cb = g_xc; n0 = bn; } else { Cb = g_z; n0 = bn - DI; }
        ld = DI;
    } else { Cb = C; n0 = bn; ld = ldc; }

    const int g = lane >> 2, t = lane & 3;
#pragma unroll
    for (int i = 0; i < 4; i++){
        const int r0 = bm + wm*64 + i*16 + g;
#pragma unroll
        for (int j = 0; j < 4; j++){
            const int col = n0 + wn*32 + j*8 + t*2;
            float2 v0 = make_float2(acc[i][j][0], acc[i][j][1]);
            float2 v1 = make_float2(acc[i][j][2], acc[i][j][3]);
            *(float2*)(Cb + (size_t)r0       * ld + col) = v0;
            *(float2*)(Cb + (size_t)(r0 + 8) * ld + col) = v1;
        }
    }
}

// ---------------- fp32 -> (hi,lo) fp16 split ----------------------------------
__global__ __launch_bounds__(256)
void split_fp16(const float* __restrict__ in, __half* __restrict__ hi,
                __half* __restrict__ lo, int n4)
{
    int i = blockIdx.x * blockDim.x + threadIdx.x;
    if (i >= n4) return;
    float4 v = ((const float4*)in)[i];
    float a[4] = {v.x, v.y, v.z, v.w};
    __half h[4], l[4];
    #pragma unroll
    for (int k = 0; k < 4; k++){
        h[k] = __float2half_rn(a[k]);
        l[k] = __float2half_rn(a[k] - __half2float(h[k]));
    }
    ((__half2*)hi)[2*i]   = __halves2half2(h[0], h[1]);
    ((__half2*)hi)[2*i+1] = __halves2half2(h[2], h[3]);
    ((__half2*)lo)[2*i]   = __halves2half2(l[0], l[1]);
    ((__half2*)lo)[2*i+1] = __halves2half2(l[2], l[3]);
}

// ---------------- fp32 -> fp16 round (weights) --------------------------------
__global__ __launch_bounds__(256)
void cvt_fp16(const float* __restrict__ in, __half* __restrict__ out, int n4)
{
    int i = blockIdx.x * blockDim.x + threadIdx.x;
    if (i >= n4) return;
    float4 v = ((const float4*)in)[i];
    ((__half2*)out)[2*i]   = __halves2half2(__float2half_rn(v.x), __float2half_rn(v.y));
    ((__half2*)out)[2*i+1] = __halves2half2(__float2half_rn(v.z), __float2half_rn(v.w));
}

// ---------------- fp32 SIMT GEMM (delta GEMM, K=64) ---------------------------
__global__ __launch_bounds__(256)
void gemm_delta(const float* __restrict__ A, int lda,
                const float* __restrict__ W, int Kdim,
                float* __restrict__ C, int ldc,
                const float* __restrict__ bias)
{
    const int bm = blockIdx.y * 128;
    const int bn = blockIdx.x * 128;

    __shared__ float As[8][128];
    __shared__ float Bs[8][128];

    float acc[8][8];
#pragma unroll
    for (int i = 0; i < 8; i++)
#pragma unroll
        for (int j = 0; j < 8; j++) acc[i][j] = 0.f;

    const int tid  = threadIdx.x;
    const int arow = tid >> 1;
    const int acol = (tid & 1) * 4;
    const int trow = (tid >> 4) * 8;
    const int tcol = (tid & 15) * 8;

    const float* Aptr = A + (size_t)(bm + arow) * lda + acol;
    const float* Wptr = W + (size_t)(bn + arow) * Kdim + acol;

    for (int kt = 0; kt < Kdim; kt += 8) {
        float4 av = *(const float4*)(Aptr + kt);
        float4 wv = *(const float4*)(Wptr + kt);
        As[acol+0][arow] = av.x; As[acol+1][arow] = av.y;
        As[acol+2][arow] = av.z; As[acol+3][arow] = av.w;
        Bs[acol+0][arow] = wv.x; Bs[acol+1][arow] = wv.y;
        Bs[acol+2][arow] = wv.z; Bs[acol+3][arow] = wv.w;
        __syncthreads();

#pragma unroll
        for (int kk = 0; kk < 8; kk++) {
            float4 a0 = *(const float4*)&As[kk][trow];
            float4 a1 = *(const float4*)&As[kk][trow+4];
            float4 b0 = *(const float4*)&Bs[kk][tcol];
            float4 b1 = *(const float4*)&Bs[kk][tcol+4];
            float ar[8] = {a0.x,a0.y,a0.z,a0.w,a1.x,a1.y,a1.z,a1.w};
            float br[8] = {b0.x,b0.y,b0.z,b0.w,b1.x,b1.y,b1.z,b1.w};
#pragma unroll
            for (int i = 0; i < 8; i++)
#pragma unroll
                for (int j = 0; j < 8; j++)
                    acc[i][j] = fmaf(ar[i], br[j], acc[i][j]);
        }
        __syncthreads();
    }

#pragma unroll
    for (int i = 0; i < 8; i++) {
        const int m = bm + trow + i;
#pragma unroll
        for (int j = 0; j < 8; j++) {
            const int n = bn + tcol + j;
            float v = acc[i][j] + bias[n];
            float sp = (v > 20.f) ? v : log1pf(__expf(v));
            C[(size_t)m * ldc + n] = sp;
        }
    }
}

// ---------------- small tiled GEMM for dBC (N=96) ----------------------------
__global__ __launch_bounds__(256)
void gemm_small(const float* __restrict__ A, int lda,
                const float* __restrict__ W, int Kdim,
                float* __restrict__ C, int ldc)
{
    const int bm = blockIdx.y * 32;
    const int bn = blockIdx.x * 32;

    __shared__ float As[32][33];
    __shared__ float Ws[32][33];

    float acc[2][2] = {{0.f,0.f},{0.f,0.f}};

    const int tid  = threadIdx.x;
    const int lrow = tid >> 3;
    const int lcol = (tid & 7) * 4;
    const int tm   = (tid >> 4) * 2;
    const int tn   = (tid & 15) * 2;

    for (int kt = 0; kt < Kdim; kt += 32) {
        float4 av = *(const float4*)(A + (size_t)(bm + lrow) * lda + kt + lcol);
        float4 wv = *(const float4*)(W + (size_t)(bn + lrow) * Kdim + kt + lcol);
        As[lcol+0][lrow] = av.x; As[lcol+1][lrow] = av.y;
        As[lcol+2][lrow] = av.z; As[lcol+3][lrow] = av.w;
        Ws[lcol+0][lrow] = wv.x; Ws[lcol+1][lrow] = wv.y;
        Ws[lcol+2][lrow] = wv.z; Ws[lcol+3][lrow] = wv.w;
        __syncthreads();

#pragma unroll
        for (int kk = 0; kk < 32; kk++) {
            float a0 = As[kk][tm], a1 = As[kk][tm+1];
            float b0 = Ws[kk][tn], b1 = Ws[kk][tn+1];
            acc[0][0] = fmaf(a0, b0, acc[0][0]);
            acc[0][1] = fmaf(a0, b1, acc[0][1]);
            acc[1][0] = fmaf(a1, b0, acc[1][0]);
            acc[1][1] = fmaf(a1, b1, acc[1][1]);
        }
        __syncthreads();
    }

#pragma unroll
    for (int i = 0; i < 2; i++)
#pragma unroll
        for (int j = 0; j < 2; j++)
            C[(size_t)(bm + tm + i) * ldc + (bn + tn + j)] = acc[i][j];
}

// ---------------- depthwise causal conv (K=4) + bias + SiLU ------------------
__global__ __launch_bounds__(256)
void conv_silu_kernel(const float* __restrict__ cw, const float* __restrict__ cb)
{
    int idx = blockIdx.x * blockDim.x + threadIdx.x;
    if (idx >= BL * DI) return;
    int d  = idx % DI;
    int bl = idx / DI;
    int l  = bl % L_;
    int b  = bl / L_;

    float s = cb[d];
    const float* base = g_xc + (size_t)b * L_ * DI + d;
#pragma unroll
    for (int j = 0; j < KC; j++) {
        int ll = l + j - (KC - 1);
        if (ll >= 0) s = fmaf(base[(size_t)ll * DI], cw[d * KC + j], s);
    }
    g_xca[idx] = s / (1.f + __expf(-s));
}

// ---------------- selective scan + gate (R6 version) --------------------------
__global__ __launch_bounds__(256)
void scan_kernel(const float* __restrict__ A_log, const float* __restrict__ Dp)
{
    const int gtid = blockIdx.x * blockDim.x + threadIdx.x;
    const int warp = gtid >> 5;
    const int lane = threadIdx.x & 31;
    const int half = lane >> 4;
    const int n    = lane & 15;
    const int c    = warp * 2 + half;
    const int b    = c / DI;
    const int d    = c % DI;

    const float Aval = -__expf(A_log[d * DS + n]);
    const float dp   = Dp[d];

    const size_t rbase = (size_t)b * L_ * DI + d;
    const float* pD = g_del + rbase;
    const float* pX = g_xca + rbase;
    const float* pZ = g_z   + rbase;
    const float* pB = g_dBC + (size_t)b * L_ * 96 + DTR + n;
    const float* pC = g_dBC + (size_t)b * L_ * 96 + DTR + DS + n;
    __half* pUh = g_uh + rbase;
    __half* pUl = g_ul + rbase;

    float h = 0.f;
    float dlt = pD[0], xv = pX[0], zv = pZ[0], Bn = pB[0], Cn = pC[0];

    for (int l = 0; l < L_; l++) {
        const int ln = (l + 1 < L_) ? (l + 1) : l;
        float dlt_n = pD[(size_t)ln * DI];
        float xv_n  = pX[(size_t)ln * DI];
        float zv_n  = pZ[(size_t)ln * DI];
        float Bn_n  = pB[(size_t)ln * 96];
        float Cn_n  = pC[(size_t)ln * 96];

        float a = __expf(dlt * Aval);
        h = fmaf(a, h, dlt * Bn * xv);
        float p = h * Cn;
        p += __shfl_xor_sync(0xffffffffu, p, 8);
        p += __shfl_xor_sync(0xffffffffu, p, 4);
        p += __shfl_xor_sync(0xffffffffu, p, 2);
        p += __shfl_xor_sync(0xffffffffu, p, 1);
        if (n == 0) {
            float y  = fmaf(dp, xv, p);
            float sz = zv / (1.f + __expf(-zv));
            float u  = y * sz;
            __half uh = __float2half_rn(u);
            __half ul = __float2half_rn(u - __half2float(uh));
            pUh[(size_t)l * DI] = uh;
            pUl[(size_t)l * DI] = ul;
        }
        dlt = dlt_n; xv = xv_n; zv = zv_n; Bn = Bn_n; Cn = Cn_n;
    }
}

// ---------------- launch ------------------------------------------------------
extern "C" void kernel_launch(void* const* d_in, const int* in_sizes, int n_in,
                              void* d_out, int out_size)
{
    const float* x      = (const float*)d_in[0];
    const float* W_in   = (const float*)d_in[1];
    const float* conv_w = (const float*)d_in[2];
    const float* conv_b = (const float*)d_in[3];
    const float* W_x    = (const float*)d_in[4];
    const float* W_dt   = (const float*)d_in[5];
    const float* b_dt   = (const float*)d_in[6];
    const float* A_log  = (const float*)d_in[7];
    const float* Dp     = (const float*)d_in[8];
    const float* W_out  = (const float*)d_in[9];
    float* out = (float*)d_out;

    float* p_xca; cudaGetSymbolAddress((void**)&p_xca, g_xca);
    float* p_dBC; cudaGetSymbolAddress((void**)&p_dBC, g_dBC);
    float* p_del; cudaGetSymbolAddress((void**)&p_del, g_del);

    __half *p_xh, *p_xl, *p_wih, *p_uh, *p_ul, *p_woh;
    cudaGetSymbolAddress((void**)&p_xh,  g_xh);
    cudaGetSymbolAddress((void**)&p_xl,  g_xl);
    cudaGetSymbolAddress((void**)&p_wih, g_wih);
    cudaGetSymbolAddress((void**)&p_uh,  g_uh);
    cudaGetSymbolAddress((void**)&p_ul,  g_ul);
    cudaGetSymbolAddress((void**)&p_woh, g_woh);

    cudaFuncSetAttribute(mma_gemm<0>, cudaFuncAttributeMaxDynamicSharedMemorySize, MMA_SMEM);
    cudaFuncSetAttribute(mma_gemm<1>, cudaFuncAttributeMaxDynamicSharedMemorySize, MMA_SMEM);

    // launches 1-3: conversions (W_out cvt moved early so GEMM1 sits in the
    // profiled 4th launch slot)
    {
        int n4 = (BL * DM) / 4;
        split_fp16<<<(n4 + 255) / 256, 256>>>(x, p_xh, p_xl, n4);          // 1
        n4 = (2 * DI * DM) / 4;
        cvt_fp16<<<(n4 + 255) / 256, 256>>>(W_in, p_wih, n4);              // 2
        n4 = (DM * DI) / 4;
        cvt_fp16<<<(n4 + 255) / 256, 256>>>(W_out, p_woh, n4);             // 3
    }
    // 4) xz = x @ W_in^T  (HMMA fp16x2, 128x64 tiles) -> g_xc / g_z
    {
        dim3 grid(2 * DI / 64, BL / 128);    // (64, 16) = 1024 CTAs
        mma_gemm<1><<<grid, 128, MMA_SMEM>>>(p_xh, p_xl, p_wih, DM, nullptr, 0);
    }
    // 5) depthwise causal conv + bias + silu -> g_xca
    {
        int total = BL * DI;
        conv_silu_kernel<<<(total + 255) / 256, 256>>>(conv_w, conv_b);
    }
    // 6) dBC = xca @ W_x^T   [BL,96]
    {
        dim3 grid(96 / 32, BL / 32);
        gemm_small<<<grid, 256>>>(p_xca, DI, W_x, DI, p_dBC, 96);
    }
    // 7) delta = softplus(dBC[:, :64] @ W_dt^T + b_dt)  [BL, DI]
    {
        dim3 grid(DI / 128, BL / 128);
        gemm_delta<<<grid, 256>>>(p_dBC, 96, W_dt, DTR, p_del, DI, b_dt);
    }
    // 8) selective scan + D skip + gate -> g_uh/g_ul
    {
        scan_kernel<<<(B_ * DI / 2) * 32 / 256, 256>>>(A_log, Dp);
    }
    // 9) out = u @ W_out^T  (HMMA fp16x2, 128x64 tiles)
    {
        dim3 grid(DM / 64, BL / 128);        // (16, 16) = 256 CTAs
        mma_gemm<0><<<grid, 128, MMA_SMEM>>>(p_uh, p_ul, p_woh, DI, out, DM);
    }
}

// round 10
// speedup vs baseline: 1.5209x; 1.1210x over previous
#include <cuda_runtime.h>
#include <cuda_fp16.h>
#include <math.h>
#include <stdint.h>

// Problem constants
#define B_  2
#define L_  1024
#define DM  1024
#define DI  2048
#define DS  16
#define DTR 64
#define KC  4
#define BL  (B_*L_)   // 2048

// ---------------- scratch (device globals) -----------------------------------
__device__ float g_xc [BL*DI];
__device__ float g_z  [BL*DI];
__device__ float g_xca[BL*DI];
__device__ float g_dBC[BL*96];
__device__ float g_del[BL*DI];

// fp16 operands for tensor-core GEMMs (A split hi/lo, B rounded once)
__device__ __half g_xh [BL*DM];
__device__ __half g_xl [BL*DM];
__device__ __half g_wih[2*DI*DM];
__device__ __half g_uh [BL*DI];
__device__ __half g_ul [BL*DI];
__device__ __half g_woh[DM*DI];

// ======================= PTX helpers (sm_80 baseline) =========================
__device__ __forceinline__ uint32_t smem_u32(const void* p){
    uint32_t a;
    asm("{ .reg .u64 t; cvta.to.shared.u64 t, %1; cvt.u32.u64 %0, t; }" : "=r"(a) : "l"(p));
    return a;
}
__device__ __forceinline__ void cp16(uint32_t dst, const void* src){
    asm volatile("cp.async.cg.shared.global [%0], [%1], 16;" :: "r"(dst), "l"(src));
}
__device__ __forceinline__ void cp_commit(){ asm volatile("cp.async.commit_group;" ::: "memory"); }
template<int N> __device__ __forceinline__ void cp_wait(){
    asm volatile("cp.async.wait_group %0;" :: "n"(N) : "memory");
}
__device__ __forceinline__ void ldsm_x4(uint32_t* r, uint32_t addr){
    asm volatile("ldmatrix.sync.aligned.m8n8.x4.shared.b16 {%0,%1,%2,%3}, [%4];"
        : "=r"(r[0]), "=r"(r[1]), "=r"(r[2]), "=r"(r[3]) : "r"(addr));
}
__device__ __forceinline__ void mma16816(float* c, const uint32_t* a, const uint32_t* b){
    asm volatile(
        "mma.sync.aligned.m16n8k16.row.col.f32.f16.f16.f32 "
        "{%0,%1,%2,%3}, {%4,%5,%6,%7}, {%8,%9}, {%0,%1,%2,%3};"
        : "+f"(c[0]), "+f"(c[1]), "+f"(c[2]), "+f"(c[3])
        : "r"(a[0]), "r"(a[1]), "r"(a[2]), "r"(a[3]), "r"(b[0]), "r"(b[1]));
}

// ===== HMMA GEMM v4: 128x128 CTA, 8 warps, warp 64x32, fp16x2, 3-stage ========
// One __syncthreads per K-chunk; loads issued 2 chunks ahead.
// MODE 0: plain store. MODE 1: split g_xc/g_z at DI boundary.
#define RSB   80
#define ARR   (128*RSB)          // 10240 bytes per operand array
#define STG   (3*ARR)            // 30720 bytes per stage (Ah, Al, Bh)
#define NSTG  3
#define MMA_SMEM (NSTG*STG)      // 92160

template<int MODE>
__global__ __launch_bounds__(256, 2)
void mma_gemm(const __half* __restrict__ Ah, const __half* __restrict__ Al,
              const __half* __restrict__ Bh,
              int Kdim, float* __restrict__ C, int ldc)
{
    extern __shared__ char sraw[];
    const uint32_t base = smem_u32(sraw);

    const int tid  = threadIdx.x;
    const int wid  = tid >> 5, lane = tid & 31;
    const int wm   = wid & 1;          // 2 warp-rows of 64
    const int wn   = wid >> 1;         // 4 warp-cols of 32
    const int bm   = blockIdx.y * 128, bn = blockIdx.x * 128;

    float acc[4][4][4];
#pragma unroll
    for (int i = 0; i < 4; i++)
#pragma unroll
        for (int j = 0; j < 4; j++)
#pragma unroll
            for (int q = 0; q < 4; q++) acc[i][j][q] = 0.f;

    // stage loaders: 2 threads per row, 32B each, 3 arrays
    const int  row = tid >> 1;
    const int  hs  = tid & 1;
    const char* sAh = (const char*)(Ah + (size_t)(bm + row) * Kdim) + hs*32;
    const char* sAl = (const char*)(Al + (size_t)(bm + row) * Kdim) + hs*32;
    const char* sBh = (const char*)(Bh + (size_t)(bn + row) * Kdim) + hs*32;
    const uint32_t dst0 = base + row*RSB + hs*32;

    #define LOAD_STAGE(c, st) do {                                          \
        uint32_t d = dst0 + (st)*STG;                                        \
        size_t   g = (size_t)(c)*64;                                         \
        cp16(d,          sAh+g); cp16(d+16,          sAh+g+16);              \
        cp16(d+ARR,      sAl+g); cp16(d+ARR+16,      sAl+g+16);              \
        cp16(d+2*ARR,    sBh+g); cp16(d+2*ARR+16,    sBh+g+16);              \
    } while(0)

    // prologue: chunks 0 and 1
    LOAD_STAGE(0, 0); cp_commit();
    LOAD_STAGE(1, 1); cp_commit();

    const uint32_t aoff = base + (uint32_t)((wm*64 + (lane & 15))*RSB + (lane >> 4)*16);
    const uint32_t boff = base + 2*ARR + (uint32_t)((wn*32 + (lane & 15))*RSB + (lane >> 4)*16);

    const int NCH = Kdim >> 5;
    int sc = 0;                          // compute-stage index = c % 3
    int sl = 2;                          // load-stage index   = (c+2) % 3
    for (int c = 0; c < NCH; c++){
        cp_wait<1>();                    // chunk c resident
        __syncthreads();                 // stage 'sl' free (consumed at c-1)

        if (c + 2 < NCH) LOAD_STAGE(c + 2, sl);
        cp_commit();                     // commit every iter (empty ok)

        const uint32_t so = (uint32_t)sc * STG;
#pragma unroll
        for (int ks = 0; ks < 2; ks++){
            uint32_t ah[4][4], al[4][4];
#pragma unroll
            for (int i = 0; i < 4; i++){
                ldsm_x4(ah[i], aoff + so +       (uint32_t)(i*16*RSB + ks*32));
                ldsm_x4(al[i], aoff + so + ARR + (uint32_t)(i*16*RSB + ks*32));
            }
            uint32_t bh[2][4];
#pragma unroll
            for (int jp = 0; jp < 2; jp++)
                ldsm_x4(bh[jp], boff + so + (uint32_t)(jp*16*RSB + ks*32));
#pragma unroll
            for (int i = 0; i < 4; i++){
#pragma unroll
                for (int j = 0; j < 4; j++){
                    uint32_t bfh[2] = { bh[j>>1][j&1], bh[j>>1][2+(j&1)] };
                    mma16816(acc[i][j], ah[i], bfh);
                    mma16816(acc[i][j], al[i], bfh);
                }
            }
        }
        sc = (sc == 2) ? 0 : sc + 1;
        sl = (sl == 2) ? 0 : sl + 1;
    }
    #undef LOAD_STAGE

    // ---- epilogue ----
    float* Cb; int n0; int ld;
    if (MODE == 1){
        if (bn < DI){ Cb = g_xc; n0 = bn; } else { Cb = g_z; n0 = bn - DI; }
        ld = DI;
    } else { Cb = C; n0 = bn; ld = ldc; }

    const int g = lane >> 2, t = lane & 3;
#pragma unroll
    for (int i = 0; i < 4; i++){
        const int r0 = bm + wm*64 + i*16 + g;
#pragma unroll
        for (int j = 0; j < 4; j++){
            const int col = n0 + wn*32 + j*8 + t*2;
            float2 v0 = make_float2(acc[i][j][0], acc[i][j][1]);
            float2 v1 = make_float2(acc[i][j][2], acc[i][j][3]);
            *(float2*)(Cb + (size_t)r0       * ld + col) = v0;
            *(float2*)(Cb + (size_t)(r0 + 8) * ld + col) = v1;
        }
    }
}

// ---------------- fp32 -> (hi,lo) fp16 split ----------------------------------
__global__ __launch_bounds__(256)
void split_fp16(const float* __restrict__ in, __half* __restrict__ hi,
                __half* __restrict__ lo, int n4)
{
    int i = blockIdx.x * blockDim.x + threadIdx.x;
    if (i >= n4) return;
    float4 v = ((const float4*)in)[i];
    float a[4] = {v.x, v.y, v.z, v.w};
    __half h[4], l[4];
    #pragma unroll
    for (int k = 0; k < 4; k++){
        h[k] = __float2half_rn(a[k]);
        l[k] = __float2half_rn(a[k] - __half2float(h[k]));
    }
    ((__half2*)hi)[2*i]   = __halves2half2(h[0], h[1]);
    ((__half2*)hi)[2*i+1] = __halves2half2(h[2], h[3]);
    ((__half2*)lo)[2*i]   = __halves2half2(l[0], l[1]);
    ((__half2*)lo)[2*i+1] = __halves2half2(l[2], l[3]);
}

// ---------------- fp32 -> fp16 round (weights) --------------------------------
__global__ __launch_bounds__(256)
void cvt_fp16(const float* __restrict__ in, __half* __restrict__ out, int n4)
{
    int i = blockIdx.x * blockDim.x + threadIdx.x;
    if (i >= n4) return;
    float4 v = ((const float4*)in)[i];
    ((__half2*)out)[2*i]   = __halves2half2(__float2half_rn(v.x), __float2half_rn(v.y));
    ((__half2*)out)[2*i+1] = __halves2half2(__float2half_rn(v.z), __float2half_rn(v.w));
}

// ---------------- fp32 SIMT GEMM (delta GEMM, K=64) ---------------------------
__global__ __launch_bounds__(256)
void gemm_delta(const float* __restrict__ A, int lda,
                const float* __restrict__ W, int Kdim,
                float* __restrict__ C, int ldc,
                const float* __restrict__ bias)
{
    const int bm = blockIdx.y * 128;
    const int bn = blockIdx.x * 128;

    __shared__ float As[8][128];
    __shared__ float Bs[8][128];

    float acc[8][8];
#pragma unroll
    for (int i = 0; i < 8; i++)
#pragma unroll
        for (int j = 0; j < 8; j++) acc[i][j] = 0.f;

    const int tid  = threadIdx.x;
    const int arow = tid >> 1;
    const int acol = (tid & 1) * 4;
    const int trow = (tid >> 4) * 8;
    const int tcol = (tid & 15) * 8;

    const float* Aptr = A + (size_t)(bm + arow) * lda + acol;
    const float* Wptr = W + (size_t)(bn + arow) * Kdim + acol;

    for (int kt = 0; kt < Kdim; kt += 8) {
        float4 av = *(const float4*)(Aptr + kt);
        float4 wv = *(const float4*)(Wptr + kt);
        As[acol+0][arow] = av.x; As[acol+1][arow] = av.y;
        As[acol+2][arow] = av.z; As[acol+3][arow] = av.w;
        Bs[acol+0][arow] = wv.x; Bs[acol+1][arow] = wv.y;
        Bs[acol+2][arow] = wv.z; Bs[acol+3][arow] = wv.w;
        __syncthreads();

#pragma unroll
        for (int kk = 0; kk < 8; kk++) {
            float4 a0 = *(const float4*)&As[kk][trow];
            float4 a1 = *(const float4*)&As[kk][trow+4];
            float4 b0 = *(const float4*)&Bs[kk][tcol];
            float4 b1 = *(const float4*)&Bs[kk][tcol+4];
            float ar[8] = {a0.x,a0.y,a0.z,a0.w,a1.x,a1.y,a1.z,a1.w};
            float br[8] = {b0.x,b0.y,b0.z,b0.w,b1.x,b1.y,b1.z,b1.w};
#pragma unroll
            for (int i = 0; i < 8; i++)
#pragma unroll
                for (int j = 0; j < 8; j++)
                    acc[i][j] = fmaf(ar[i], br[j], acc[i][j]);
        }
        __syncthreads();
    }

#pragma unroll
    for (int i = 0; i < 8; i++) {
        const int m = bm + trow + i;
#pragma unroll
        for (int j = 0; j < 8; j++) {
            const int n = bn + tcol + j;
            float v = acc[i][j] + bias[n];
            float sp = (v > 20.f) ? v : log1pf(__expf(v));
            C[(size_t)m * ldc + n] = sp;
        }
    }
}

// ---------------- small tiled GEMM for dBC (N=96) ----------------------------
__global__ __launch_bounds__(256)
void gemm_small(const float* __restrict__ A, int lda,
                const float* __restrict__ W, int Kdim,
                float* __restrict__ C, int ldc)
{
    const int bm = blockIdx.y * 32;
    const int bn = blockIdx.x * 32;

    __shared__ float As[32][33];
    __shared__ float Ws[32][33];

    float acc[2][2] = {{0.f,0.f},{0.f,0.f}};

    const int tid  = threadIdx.x;
    const int lrow = tid >> 3;
    const int lcol = (tid & 7) * 4;
    const int tm   = (tid >> 4) * 2;
    const int tn   = (tid & 15) * 2;

    for (int kt = 0; kt < Kdim; kt += 32) {
        float4 av = *(const float4*)(A + (size_t)(bm + lrow) * lda + kt + lcol);
        float4 wv = *(const float4*)(W + (size_t)(bn + lrow) * Kdim + kt + lcol);
        As[lcol+0][lrow] = av.x; As[lcol+1][lrow] = av.y;
        As[lcol+2][lrow] = av.z; As[lcol+3][lrow] = av.w;
        Ws[lcol+0][lrow] = wv.x; Ws[lcol+1][lrow] = wv.y;
        Ws[lcol+2][lrow] = wv.z; Ws[lcol+3][lrow] = wv.w;
        __syncthreads();

#pragma unroll
        for (int kk = 0; kk < 32; kk++) {
            float a0 = As[kk][tm], a1 = As[kk][tm+1];
            float b0 = Ws[kk][tn], b1 = Ws[kk][tn+1];
            acc[0][0] = fmaf(a0, b0, acc[0][0]);
            acc[0][1] = fmaf(a0, b1, acc[0][1]);
            acc[1][0] = fmaf(a1, b0, acc[1][0]);
            acc[1][1] = fmaf(a1, b1, acc[1][1]);
        }
        __syncthreads();
    }

#pragma unroll
    for (int i = 0; i < 2; i++)
#pragma unroll
        for (int j = 0; j < 2; j++)
            C[(size_t)(bm + tm + i) * ldc + (bn + tn + j)] = acc[i][j];
}

// ---------------- depthwise causal conv (K=4) + bias + SiLU ------------------
__global__ __launch_bounds__(256)
void conv_silu_kernel(const float* __restrict__ cw, const float* __restrict__ cb)
{
    int idx = blockIdx.x * blockDim.x + threadIdx.x;
    if (idx >= BL * DI) return;
    int d  = idx % DI;
    int bl = idx / DI;
    int l  = bl % L_;
    int b  = bl / L_;

    float s = cb[d];
    const float* base = g_xc + (size_t)b * L_ * DI + d;
#pragma unroll
    for (int j = 0; j < KC; j++) {
        int ll = l + j - (KC - 1);
        if (ll >= 0) s = fmaf(base[(size_t)ll * DI], cw[d * KC + j], s);
    }
    g_xca[idx] = s / (1.f + __expf(-s));
}

// ---------------- selective scan + gate (R6 version) --------------------------
__global__ __launch_bounds__(256)
void scan_kernel(const float* __restrict__ A_log, const float* __restrict__ Dp)
{
    const int gtid = blockIdx.x * blockDim.x + threadIdx.x;
    const int warp = gtid >> 5;
    const int lane = threadIdx.x & 31;
    const int half = lane >> 4;
    const int n    = lane & 15;
    const int c    = warp * 2 + half;
    const int b    = c / DI;
    const int d    = c % DI;

    const float Aval = -__expf(A_log[d * DS + n]);
    const float dp   = Dp[d];

    const size_t rbase = (size_t)b * L_ * DI + d;
    const float* pD = g_del + rbase;
    const float* pX = g_xca + rbase;
    const float* pZ = g_z   + rbase;
    const float* pB = g_dBC + (size_t)b * L_ * 96 + DTR + n;
    const float* pC = g_dBC + (size_t)b * L_ * 96 + DTR + DS + n;
    __half* pUh = g_uh + rbase;
    __half* pUl = g_ul + rbase;

    float h = 0.f;
    float dlt = pD[0], xv = pX[0], zv = pZ[0], Bn = pB[0], Cn = pC[0];

    for (int l = 0; l < L_; l++) {
        const int ln = (l + 1 < L_) ? (l + 1) : l;
        float dlt_n = pD[(size_t)ln * DI];
        float xv_n  = pX[(size_t)ln * DI];
        float zv_n  = pZ[(size_t)ln * DI];
        float Bn_n  = pB[(size_t)ln * 96];
        float Cn_n  = pC[(size_t)ln * 96];

        float a = __expf(dlt * Aval);
        h = fmaf(a, h, dlt * Bn * xv);
        float p = h * Cn;
        p += __shfl_xor_sync(0xffffffffu, p, 8);
        p += __shfl_xor_sync(0xffffffffu, p, 4);
        p += __shfl_xor_sync(0xffffffffu, p, 2);
        p += __shfl_xor_sync(0xffffffffu, p, 1);
        if (n == 0) {
            float y  = fmaf(dp, xv, p);
            float sz = zv / (1.f + __expf(-zv));
            float u  = y * sz;
            __half uh = __float2half_rn(u);
            __half ul = __float2half_rn(u - __half2float(uh));
            pUh[(size_t)l * DI] = uh;
            pUl[(size_t)l * DI] = ul;
        }
        dlt = dlt_n; xv = xv_n; zv = zv_n; Bn = Bn_n; Cn = Cn_n;
    }
}

// ---------------- launch ------------------------------------------------------
extern "C" void kernel_launch(void* const* d_in, const int* in_sizes, int n_in,
                              void* d_out, int out_size)
{
    const float* x      = (const float*)d_in[0];
    const float* W_in   = (const float*)d_in[1];
    const float* conv_w = (const float*)d_in[2];
    const float* conv_b = (const float*)d_in[3];
    const float* W_x    = (const float*)d_in[4];
    const float* W_dt   = (const float*)d_in[5];
    const float* b_dt   = (const float*)d_in[6];
    const float* A_log  = (const float*)d_in[7];
    const float* Dp     = (const float*)d_in[8];
    const float* W_out  = (const float*)d_in[9];
    float* out = (float*)d_out;

    float* p_xca; cudaGetSymbolAddress((void**)&p_xca, g_xca);
    float* p_dBC; cudaGetSymbolAddress((void**)&p_dBC, g_dBC);
    float* p_del; cudaGetSymbolAddress((void**)&p_del, g_del);

    __half *p_xh, *p_xl, *p_wih, *p_uh, *p_ul, *p_woh;
    cudaGetSymbolAddress((void**)&p_xh,  g_xh);
    cudaGetSymbolAddress((void**)&p_xl,  g_xl);
    cudaGetSymbolAddress((void**)&p_wih, g_wih);
    cudaGetSymbolAddress((void**)&p_uh,  g_uh);
    cudaGetSymbolAddress((void**)&p_ul,  g_ul);
    cudaGetSymbolAddress((void**)&p_woh, g_woh);

    cudaFuncSetAttribute(mma_gemm<0>, cudaFuncAttributeMaxDynamicSharedMemorySize, MMA_SMEM);
    cudaFuncSetAttribute(mma_gemm<1>, cudaFuncAttributeMaxDynamicSharedMemorySize, MMA_SMEM);

    // launches 1-3: conversions (keeps GEMM1 in the profiled 4th launch slot)
    {
        int n4 = (BL * DM) / 4;
        split_fp16<<<(n4 + 255) / 256, 256>>>(x, p_xh, p_xl, n4);          // 1
        n4 = (2 * DI * DM) / 4;
        cvt_fp16<<<(n4 + 255) / 256, 256>>>(W_in, p_wih, n4);              // 2
        n4 = (DM * DI) / 4;
        cvt_fp16<<<(n4 + 255) / 256, 256>>>(W_out, p_woh, n4);             // 3
    }
    // 4) xz = x @ W_in^T  (HMMA fp16x2, 3-stage) -> g_xc / g_z
    {
        dim3 grid(2 * DI / 128, BL / 128);   // (32, 16)
        mma_gemm<1><<<grid, 256, MMA_SMEM>>>(p_xh, p_xl, p_wih, DM, nullptr, 0);
    }
    // 5) depthwise causal conv + bias + silu -> g_xca
    {
        int total = BL * DI;
        conv_silu_kernel<<<(total + 255) / 256, 256>>>(conv_w, conv_b);
    }
    // 6) dBC = xca @ W_x^T   [BL,96]
    {
        dim3 grid(96 / 32, BL / 32);
        gemm_small<<<grid, 256>>>(p_xca, DI, W_x, DI, p_dBC, 96);
    }
    // 7) delta = softplus(dBC[:, :64] @ W_dt^T + b_dt)  [BL, DI]
    {
        dim3 grid(DI / 128, BL / 128);
        gemm_delta<<<grid, 256>>>(p_dBC, 96, W_dt, DTR, p_del, DI, b_dt);
    }
    // 8) selective scan + D skip + gate -> g_uh/g_ul
    {
        scan_kernel<<<(B_ * DI / 2) * 32 / 256, 256>>>(A_log, Dp);
    }
    // 9) out = u @ W_out^T  (HMMA fp16x2, 3-stage)
    {
        dim3 grid(DM / 128, BL / 128);       // (8, 16)
        mma_gemm<0><<<grid, 256, MMA_SMEM>>>(p_uh, p_ul, p_woh, DI, out, DM);
    }
}

// round 11
// speedup vs baseline: 1.5781x; 1.0376x over previous
#include <cuda_runtime.h>
#include <cuda_fp16.h>
#include <math.h>
#include <stdint.h>

// Problem constants
#define B_  2
#define L_  1024
#define DM  1024
#define DI  2048
#define DS  16
#define DTR 64
#define KC  4
#define BL  (B_*L_)   // 2048

// ---------------- scratch (device globals) -----------------------------------
__device__ float g_xc [BL*DI];
__device__ float g_z  [BL*DI];
__device__ float g_xca[BL*DI];
__device__ float g_dBC[BL*96];
__device__ float g_del[BL*DI];

// fp16 operands for tensor-core GEMMs (A split hi/lo, B rounded once)
__device__ __half g_xh [BL*DM];
__device__ __half g_xl [BL*DM];
__device__ __half g_wih[2*DI*DM];
__device__ __half g_uh [BL*DI];
__device__ __half g_ul [BL*DI];
__device__ __half g_woh[DM*DI];

// ======================= PTX helpers (sm_80 baseline) =========================
__device__ __forceinline__ uint32_t smem_u32(const void* p){
    uint32_t a;
    asm("{ .reg .u64 t; cvta.to.shared.u64 t, %1; cvt.u32.u64 %0, t; }" : "=r"(a) : "l"(p));
    return a;
}
__device__ __forceinline__ void cp16(uint32_t dst, const void* src){
    asm volatile("cp.async.cg.shared.global [%0], [%1], 16;" :: "r"(dst), "l"(src));
}
__device__ __forceinline__ void cp_commit(){ asm volatile("cp.async.commit_group;" ::: "memory"); }
template<int N> __device__ __forceinline__ void cp_wait(){
    asm volatile("cp.async.wait_group %0;" :: "n"(N) : "memory");
}
__device__ __forceinline__ void ldsm_x4(uint32_t* r, uint32_t addr){
    asm volatile("ldmatrix.sync.aligned.m8n8.x4.shared.b16 {%0,%1,%2,%3}, [%4];"
        : "=r"(r[0]), "=r"(r[1]), "=r"(r[2]), "=r"(r[3]) : "r"(addr));
}
__device__ __forceinline__ void mma16816(float* c, const uint32_t* a, const uint32_t* b){
    asm volatile(
        "mma.sync.aligned.m16n8k16.row.col.f32.f16.f16.f32 "
        "{%0,%1,%2,%3}, {%4,%5,%6,%7}, {%8,%9}, {%0,%1,%2,%3};"
        : "+f"(c[0]), "+f"(c[1]), "+f"(c[2]), "+f"(c[3])
        : "r"(a[0]), "r"(a[1]), "r"(a[2]), "r"(a[3]), "r"(b[0]), "r"(b[1]));
}

// ===== HMMA GEMM v5: 128x128 CTA, 8 warps, warp 64x32, fp16x2 =================
// 4-stage cp.async pipeline, unpadded 64B rows with XOR-swizzle (conflict-free),
// one __syncthreads per K-chunk, loads issued 3 chunks ahead.
// MODE 0: plain store. MODE 1: split g_xc/g_z at DI boundary.
#define ARR   (128*64)           // 8192 bytes per operand array (no padding)
#define STG   (3*ARR)            // 24576 bytes per stage (Ah, Al, Bh)
#define NSTG  4
#define MMA_SMEM (NSTG*STG + 1024)   // +1024 for base alignment

template<int MODE>
__global__ __launch_bounds__(256, 2)
void mma_gemm(const __half* __restrict__ Ah, const __half* __restrict__ Al,
              const __half* __restrict__ Bh,
              int Kdim, float* __restrict__ C, int ldc)
{
    extern __shared__ char sraw[];
    const uint32_t base = (smem_u32(sraw) + 1023) & ~1023u;   // bits 0-9 clear

    const int tid  = threadIdx.x;
    const int wid  = tid >> 5, lane = tid & 31;
    const int wm   = wid & 1;          // 2 warp-rows of 64
    const int wn   = wid >> 1;         // 4 warp-cols of 32
    const int bm   = blockIdx.y * 128, bn = blockIdx.x * 128;

    float acc[4][4][4];
#pragma unroll
    for (int i = 0; i < 4; i++)
#pragma unroll
        for (int j = 0; j < 4; j++)
#pragma unroll
            for (int q = 0; q < 4; q++) acc[i][j][q] = 0.f;

    // ---- stage loaders: 2 threads per row, 32B (= 2 swizzled 16B chunks) ----
    const int  row   = tid >> 1;
    const int  hs    = tid & 1;
    const int  rowsw = (row >> 1) & 3;                 // swizzle factor
    const uint32_t c0 = (uint32_t)(((2*hs)     ^ rowsw) << 4);
    const uint32_t c1 = (uint32_t)(((2*hs + 1) ^ rowsw) << 4);
    const char* sAh = (const char*)(Ah + (size_t)(bm + row) * Kdim) + hs*32;
    const char* sAl = (const char*)(Al + (size_t)(bm + row) * Kdim) + hs*32;
    const char* sBh = (const char*)(Bh + (size_t)(bn + row) * Kdim) + hs*32;
    const uint32_t dst0 = base + row*64;

    #define LOAD_STAGE(c, st) do {                                          \
        uint32_t d = dst0 + (st)*STG;                                        \
        size_t   g = (size_t)(c)*64;                                         \
        cp16(d +         c0, sAh+g); cp16(d +         c1, sAh+g+16);         \
        cp16(d + ARR   + c0, sAl+g); cp16(d + ARR   + c1, sAl+g+16);         \
        cp16(d + 2*ARR + c0, sBh+g); cp16(d + 2*ARR + c1, sBh+g+16);         \
    } while(0)

    const int NCH = Kdim >> 5;
    // prologue: chunks 0..2
    LOAD_STAGE(0, 0); cp_commit();
    if (NCH > 1) LOAD_STAGE(1, 1); cp_commit();
    if (NCH > 2) LOAD_STAGE(2, 2); cp_commit();

    // ldmatrix per-lane base addresses (swizzled chunk folded into base;
    // ks advance = XOR 32, valid because bits 4-5 of all other terms are 0)
    const int r15 = lane & 15;
    const int lch = lane >> 4;                          // logical chunk 0/1
    const int lsw = (r15 >> 1) & 3;
    const uint32_t apc = (uint32_t)((lch ^ lsw) << 4);
    const uint32_t aoff = base + (uint32_t)((wm*64 + r15)*64) + apc;
    const uint32_t boff = base + 2*ARR + (uint32_t)((wn*32 + r15)*64) + apc;

    int sc = 0;                          // compute-stage index = c % 4
    int sl = 3;                          // load-stage index   = (c+3) % 4
    for (int c = 0; c < NCH; c++){
        cp_wait<2>();                    // chunk c resident
        __syncthreads();                 // stage 'sl' free (consumed at c-1)

        if (c + 3 < NCH) LOAD_STAGE(c + 3, sl);
        cp_commit();                     // commit every iter (empty ok)

        const uint32_t so = (uint32_t)sc * STG;
#pragma unroll
        for (int ks = 0; ks < 2; ks++){
            const uint32_t kx = (uint32_t)(ks << 5);
            uint32_t ah[4][4], al[4][4];
#pragma unroll
            for (int i = 0; i < 4; i++){
                ldsm_x4(ah[i], ((aoff + so +       (uint32_t)(i*1024))) ^ kx);
                ldsm_x4(al[i], ((aoff + so + ARR + (uint32_t)(i*1024))) ^ kx);
            }
            uint32_t bh[2][4];
#pragma unroll
            for (int jp = 0; jp < 2; jp++)
                ldsm_x4(bh[jp], ((boff + so + (uint32_t)(jp*1024))) ^ kx);
#pragma unroll
            for (int i = 0; i < 4; i++){
#pragma unroll
                for (int j = 0; j < 4; j++){
                    uint32_t bfh[2] = { bh[j>>1][j&1], bh[j>>1][2+(j&1)] };
                    mma16816(acc[i][j], ah[i], bfh);
                    mma16816(acc[i][j], al[i], bfh);
                }
            }
        }
        sc = (sc == 3) ? 0 : sc + 1;
        sl = (sl == 3) ? 0 : sl + 1;
    }
    #undef LOAD_STAGE

    // ---- epilogue ----
    float* Cb; int n0; int ld;
    if (MODE == 1){
        if (bn < DI){ Cb = g_xc; n0 = bn; } else { Cb = g_z; n0 = bn - DI; }
        ld = DI;
    } else { Cb = C; n0 = bn; ld = ldc; }

    const int g = lane >> 2, t = lane & 3;
#pragma unroll
    for (int i = 0; i < 4; i++){
        const int r0 = bm + wm*64 + i*16 + g;
#pragma unroll
        for (int j = 0; j < 4; j++){
            const int col = n0 + wn*32 + j*8 + t*2;
            float2 v0 = make_float2(acc[i][j][0], acc[i][j][1]);
            float2 v1 = make_float2(acc[i][j][2], acc[i][j][3]);
            *(float2*)(Cb + (size_t)r0       * ld + col) = v0;
            *(float2*)(Cb + (size_t)(r0 + 8) * ld + col) = v1;
        }
    }
}

// ---------------- fp32 -> (hi,lo) fp16 split ----------------------------------
__global__ __launch_bounds__(256)
void split_fp16(const float* __restrict__ in, __half* __restrict__ hi,
                __half* __restrict__ lo, int n4)
{
    int i = blockIdx.x * blockDim.x + threadIdx.x;
    if (i >= n4) return;
    float4 v = ((const float4*)in)[i];
    float a[4] = {v.x, v.y, v.z, v.w};
    __half h[4], l[4];
    #pragma unroll
    for (int k = 0; k < 4; k++){
        h[k] = __float2half_rn(a[k]);
        l[k] = __float2half_rn(a[k] - __half2float(h[k]));
    }
    ((__half2*)hi)[2*i]   = __halves2half2(h[0], h[1]);
    ((__half2*)hi)[2*i+1] = __halves2half2(h[2], h[3]);
    ((__half2*)lo)[2*i]   = __halves2half2(l[0], l[1]);
    ((__half2*)lo)[2*i+1] = __halves2half2(l[2], l[3]);
}

// ---------------- fp32 -> fp16 round (weights) --------------------------------
__global__ __launch_bounds__(256)
void cvt_fp16(const float* __restrict__ in, __half* __restrict__ out, int n4)
{
    int i = blockIdx.x * blockDim.x + threadIdx.x;
    if (i >= n4) return;
    float4 v = ((const float4*)in)[i];
    ((__half2*)out)[2*i]   = __halves2half2(__float2half_rn(v.x), __float2half_rn(v.y));
    ((__half2*)out)[2*i+1] = __halves2half2(__float2half_rn(v.z), __float2half_rn(v.w));
}

// ---------------- fp32 SIMT GEMM (delta GEMM, K=64) ---------------------------
__global__ __launch_bounds__(256)
void gemm_delta(const float* __restrict__ A, int lda,
                const float* __restrict__ W, int Kdim,
                float* __restrict__ C, int ldc,
                const float* __restrict__ bias)
{
    const int bm = blockIdx.y * 128;
    const int bn = blockIdx.x * 128;

    __shared__ float As[8][128];
    __shared__ float Bs[8][128];

    float acc[8][8];
#pragma unroll
    for (int i = 0; i < 8; i++)
#pragma unroll
        for (int j = 0; j < 8; j++) acc[i][j] = 0.f;

    const int tid  = threadIdx.x;
    const int arow = tid >> 1;
    const int acol = (tid & 1) * 4;
    const int trow = (tid >> 4) * 8;
    const int tcol = (tid & 15) * 8;

    const float* Aptr = A + (size_t)(bm + arow) * lda + acol;
    const float* Wptr = W + (size_t)(bn + arow) * Kdim + acol;

    for (int kt = 0; kt < Kdim; kt += 8) {
        float4 av = *(const float4*)(Aptr + kt);
        float4 wv = *(const float4*)(Wptr + kt);
        As[acol+0][arow] = av.x; As[acol+1][arow] = av.y;
        As[acol+2][arow] = av.z; As[acol+3][arow] = av.w;
        Bs[acol+0][arow] = wv.x; Bs[acol+1][arow] = wv.y;
        Bs[acol+2][arow] = wv.z; Bs[acol+3][arow] = wv.w;
        __syncthreads();

#pragma unroll
        for (int kk = 0; kk < 8; kk++) {
            float4 a0 = *(const float4*)&As[kk][trow];
            float4 a1 = *(const float4*)&As[kk][trow+4];
            float4 b0 = *(const float4*)&Bs[kk][tcol];
            float4 b1 = *(const float4*)&Bs[kk][tcol+4];
            float ar[8] = {a0.x,a0.y,a0.z,a0.w,a1.x,a1.y,a1.z,a1.w};
            float br[8] = {b0.x,b0.y,b0.z,b0.w,b1.x,b1.y,b1.z,b1.w};
#pragma unroll
            for (int i = 0; i < 8; i++)
#pragma unroll
                for (int j = 0; j < 8; j++)
                    acc[i][j] = fmaf(ar[i], br[j], acc[i][j]);
        }
        __syncthreads();
    }

#pragma unroll
    for (int i = 0; i < 8; i++) {
        const int m = bm + trow + i;
#pragma unroll
        for (int j = 0; j < 8; j++) {
            const int n = bn + tcol + j;
            float v = acc[i][j] + bias[n];
            float sp = (v > 20.f) ? v : log1pf(__expf(v));
            C[(size_t)m * ldc + n] = sp;
        }
    }
}

// ---------------- small tiled GEMM for dBC (N=96) ----------------------------
__global__ __launch_bounds__(256)
void gemm_small(const float* __restrict__ A, int lda,
                const float* __restrict__ W, int Kdim,
                float* __restrict__ C, int ldc)
{
    const int bm = blockIdx.y * 32;
    const int bn = blockIdx.x * 32;

    __shared__ float As[32][33];
    __shared__ float Ws[32][33];

    float acc[2][2] = {{0.f,0.f},{0.f,0.f}};

    const int tid  = threadIdx.x;
    const int lrow = tid >> 3;
    const int lcol = (tid & 7) * 4;
    const int tm   = (tid >> 4) * 2;
    const int tn   = (tid & 15) * 2;

    for (int kt = 0; kt < Kdim; kt += 32) {
        float4 av = *(const float4*)(A + (size_t)(bm + lrow) * lda + kt + lcol);
        float4 wv = *(const float4*)(W + (size_t)(bn + lrow) * Kdim + kt + lcol);
        As[lcol+0][lrow] = av.x; As[lcol+1][lrow] = av.y;
        As[lcol+2][lrow] = av.z; As[lcol+3][lrow] = av.w;
        Ws[lcol+0][lrow] = wv.x; Ws[lcol+1][lrow] = wv.y;
        Ws[lcol+2][lrow] = wv.z; Ws[lcol+3][lrow] = wv.w;
        __syncthreads();

#pragma unroll
        for (int kk = 0; kk < 32; kk++) {
            float a0 = As[kk][tm], a1 = As[kk][tm+1];
            float b0 = Ws[kk][tn], b1 = Ws[kk][tn+1];
            acc[0][0] = fmaf(a0, b0, acc[0][0]);
            acc[0][1] = fmaf(a0, b1, acc[0][1]);
            acc[1][0] = fmaf(a1, b0, acc[1][0]);
            acc[1][1] = fmaf(a1, b1, acc[1][1]);
        }
        __syncthreads();
    }

#pragma unroll
    for (int i = 0; i < 2; i++)
#pragma unroll
        for (int j = 0; j < 2; j++)
            C[(size_t)(bm + tm + i) * ldc + (bn + tn + j)] = acc[i][j];
}

// ---------------- depthwise causal conv (K=4) + bias + SiLU ------------------
__global__ __launch_bounds__(256)
void conv_silu_kernel(const float* __restrict__ cw, const float* __restrict__ cb)
{
    int idx = blockIdx.x * blockDim.x + threadIdx.x;
    if (idx >= BL * DI) return;
    int d  = idx % DI;
    int bl = idx / DI;
    int l  = bl % L_;
    int b  = bl / L_;

    float s = cb[d];
    const float* base = g_xc + (size_t)b * L_ * DI + d;
#pragma unroll
    for (int j = 0; j < KC; j++) {
        int ll = l + j - (KC - 1);
        if (ll >= 0) s = fmaf(base[(size_t)ll * DI], cw[d * KC + j], s);
    }
    g_xca[idx] = s / (1.f + __expf(-s));
}

// ---------------- selective scan + gate (R6 body, 64-thread blocks) -----------
__global__ __launch_bounds__(64)
void scan_kernel(const float* __restrict__ A_log, const float* __restrict__ Dp)
{
    const int gtid = blockIdx.x * 64 + threadIdx.x;
    const int warp = gtid >> 5;
    const int lane = threadIdx.x & 31;
    const int half = lane >> 4;
    const int n    = lane & 15;
    const int c    = warp * 2 + half;
    const int b    = c / DI;
    const int d    = c % DI;

    const float Aval = -__expf(A_log[d * DS + n]);
    const float dp   = Dp[d];

    const size_t rbase = (size_t)b * L_ * DI + d;
    const float* pD = g_del + rbase;
    const float* pX = g_xca + rbase;
    const float* pZ = g_z   + rbase;
    const float* pB = g_dBC + (size_t)b * L_ * 96 + DTR + n;
    const float* pC = g_dBC + (size_t)b * L_ * 96 + DTR + DS + n;
    __half* pUh = g_uh + rbase;
    __half* pUl = g_ul + rbase;

    float h = 0.f;
    float dlt = pD[0], xv = pX[0], zv = pZ[0], Bn = pB[0], Cn = pC[0];

    for (int l = 0; l < L_; l++) {
        const int ln = (l + 1 < L_) ? (l + 1) : l;
        float dlt_n = pD[(size_t)ln * DI];
        float xv_n  = pX[(size_t)ln * DI];
        float zv_n  = pZ[(size_t)ln * DI];
        float Bn_n  = pB[(size_t)ln * 96];
        float Cn_n  = pC[(size_t)ln * 96];

        float a = __expf(dlt * Aval);
        h = fmaf(a, h, dlt * Bn * xv);
        float p = h * Cn;
        p += __shfl_xor_sync(0xffffffffu, p, 8);
        p += __shfl_xor_sync(0xffffffffu, p, 4);
        p += __shfl_xor_sync(0xffffffffu, p, 2);
        p += __shfl_xor_sync(0xffffffffu, p, 1);
        if (n == 0) {
            float y  = fmaf(dp, xv, p);
            float sz = zv / (1.f + __expf(-zv));
            float u  = y * sz;
            __half uh = __float2half_rn(u);
            __half ul = __float2half_rn(u - __half2float(uh));
            pUh[(size_t)l * DI] = uh;
            pUl[(size_t)l * DI] = ul;
        }
        dlt = dlt_n; xv = xv_n; zv = zv_n; Bn = Bn_n; Cn = Cn_n;
    }
}

// ---------------- launch ------------------------------------------------------
extern "C" void kernel_launch(void* const* d_in, const int* in_sizes, int n_in,
                              void* d_out, int out_size)
{
    const float* x      = (const float*)d_in[0];
    const float* W_in   = (const float*)d_in[1];
    const float* conv_w = (const float*)d_in[2];
    const float* conv_b = (const float*)d_in[3];
    const float* W_x    = (const float*)d_in[4];
    const float* W_dt   = (const float*)d_in[5];
    const float* b_dt   = (const float*)d_in[6];
    const float* A_log  = (const float*)d_in[7];
    const float* Dp     = (const float*)d_in[8];
    const float* W_out  = (const float*)d_in[9];
    float* out = (float*)d_out;

    float* p_xca; cudaGetSymbolAddress((void**)&p_xca, g_xca);
    float* p_dBC; cudaGetSymbolAddress((void**)&p_dBC, g_dBC);
    float* p_del; cudaGetSymbolAddress((void**)&p_del, g_del);

    __half *p_xh, *p_xl, *p_wih, *p_uh, *p_ul, *p_woh;
    cudaGetSymbolAddress((void**)&p_xh,  g_xh);
    cudaGetSymbolAddress((void**)&p_xl,  g_xl);
    cudaGetSymbolAddress((void**)&p_wih, g_wih);
    cudaGetSymbolAddress((void**)&p_uh,  g_uh);
    cudaGetSymbolAddress((void**)&p_ul,  g_ul);
    cudaGetSymbolAddress((void**)&p_woh, g_woh);

    cudaFuncSetAttribute(mma_gemm<0>, cudaFuncAttributeMaxDynamicSharedMemorySize, MMA_SMEM);
    cudaFuncSetAttribute(mma_gemm<1>, cudaFuncAttributeMaxDynamicSharedMemorySize, MMA_SMEM);

    // launches 1-3: conversions (keeps GEMM1 in the profiled 4th launch slot)
    {
        int n4 = (BL * DM) / 4;
        split_fp16<<<(n4 + 255) / 256, 256>>>(x, p_xh, p_xl, n4);          // 1
        n4 = (2 * DI * DM) / 4;
        cvt_fp16<<<(n4 + 255) / 256, 256>>>(W_in, p_wih, n4);              // 2
        n4 = (DM * DI) / 4;
        cvt_fp16<<<(n4 + 255) / 256, 256>>>(W_out, p_woh, n4);             // 3
    }
    // 4) xz = x @ W_in^T  (HMMA fp16x2, 4-stage swizzled) -> g_xc / g_z
    {
        dim3 grid(2 * DI / 128, BL / 128);   // (32, 16)
        mma_gemm<1><<<grid, 256, MMA_SMEM>>>(p_xh, p_xl, p_wih, DM, nullptr, 0);
    }
    // 5) depthwise causal conv + bias + silu -> g_xca
    {
        int total = BL * DI;
        conv_silu_kernel<<<(total + 255) / 256, 256>>>(conv_w, conv_b);
    }
    // 6) dBC = xca @ W_x^T   [BL,96]
    {
        dim3 grid(96 / 32, BL / 32);
        gemm_small<<<grid, 256>>>(p_xca, DI, W_x, DI, p_dBC, 96);
    }
    // 7) delta = softplus(dBC[:, :64] @ W_dt^T + b_dt)  [BL, DI]
    {
        dim3 grid(DI / 128, BL / 128);
        gemm_delta<<<grid, 256>>>(p_dBC, 96, W_dt, DTR, p_del, DI, b_dt);
    }
    // 8) selective scan + D skip + gate -> g_uh/g_ul (64-thread blocks)
    {
        scan_kernel<<<B_ * DI / 4, 64>>>(A_log, Dp);
    }
    // 9) out = u @ W_out^T  (HMMA fp16x2, 4-stage swizzled)
    {
        dim3 grid(DM / 128, BL / 128);       // (8, 16)
        mma_gemm<0><<<grid, 256, MMA_SMEM>>>(p_uh, p_ul, p_woh, DI, out, DM);
    }
}